// round 2
// baseline (speedup 1.0000x reference)
#include <cuda_runtime.h>
#include <cuda_bf16.h>
#include <cstdint>
#include <cstddef>

#define Hdim 1024
#define Edim 18432
#define Vdim 32000
#define Tlen 15
#define NBLK 148
#define NTHR 1024

struct State {
    float feat[Hdim];
    float h[Hdim], c[Hdim];
    float tmph[Hdim], tmpc[Hdim];
    float h1[Hdim], c1[Hdim];
    float h2[2][Hdim], c2[2][Hdim];
    float h3[2][Hdim], c3[2][Hdim];
    float word[Hdim];
    float hi[Vdim];
    unsigned long long lomax;
    unsigned bar_count, bar_gen;
};
__device__ State g_s;
__device__ unsigned g_fcw[(size_t)Vdim * (Hdim / 2)];   // bf16x2-packed fc_w copy (65.5 MB)

__device__ __forceinline__ float warp_sum(float s) {
#pragma unroll
    for (int o = 16; o; o >>= 1) s += __shfl_xor_sync(0xffffffffu, s, o);
    return s;
}
__device__ __forceinline__ float sigf(float x) { return 1.0f / (1.0f + expf(-x)); }
__device__ __forceinline__ void barn(int id) {
    asm volatile("bar.sync %0, 128;" :: "r"(id) : "memory");
}

// sense-reversing software grid barrier; all NBLK blocks resident (1/SM)
__device__ __forceinline__ void grid_bar() {
    __syncthreads();
    if (threadIdx.x == 0) {
        __threadfence();
        volatile unsigned* vgen = &g_s.bar_gen;
        unsigned g = *vgen;
        unsigned a = atomicAdd(&g_s.bar_count, 1u);
        if (a == NBLK - 1) {
            atomicExch(&g_s.bar_count, 0u);
            __threadfence();
            atomicAdd(&g_s.bar_gen, 1u);
        } else {
            while (*vgen == g) __nanosleep(32);
        }
        __threadfence();
    }
    __syncthreads();
}

__device__ __forceinline__ unsigned long long packkey(float v, unsigned idx) {
    unsigned u = __float_as_uint(v);
    u = (u & 0x80000000u) ? ~u : (u | 0x80000000u);
    return ((unsigned long long)u << 32) | (unsigned long long)(0xFFFFFFFFu - idx);
}
__device__ __forceinline__ float key_val(unsigned long long k) {
    unsigned u = (unsigned)(k >> 32);
    u = (u & 0x80000000u) ? (u ^ 0x80000000u) : ~u;
    return __uint_as_float(u);
}
__device__ __forceinline__ int key_idx(unsigned long long k) {
    return (int)(0xFFFFFFFFu - (unsigned)(k & 0xFFFFFFFFull));
}

// LSTM cell: group of 4 warps handles one hidden row (warp wg = gate wg of i,f,g,o).
// Cross-block-mutable vectors are read via __ldcg (L2) to dodge stale L1.
__device__ __forceinline__ void phase_cell(
    const float* __restrict__ x, const float* __restrict__ hin, const float* __restrict__ cin,
    const float* __restrict__ wih, const float* __restrict__ whh,
    const float* __restrict__ bih, const float* __restrict__ bhh,
    float* __restrict__ hout, float* __restrict__ cout,
    float* sred, int row, int group, int wg, int lane)
{
    if (row >= Hdim) return;
    const float4* Wi = (const float4*)(wih + ((size_t)wg * Hdim + row) * Hdim);
    const float4* Wh = (const float4*)(whh + ((size_t)wg * Hdim + row) * Hdim);
    const float4* X  = (const float4*)x;
    const float4* Hv = (const float4*)hin;
    float s = 0.f;
#pragma unroll
    for (int k = 0; k < 8; k++) {
        int q = lane + 32 * k;
        float4 a = Wi[q], b = __ldcg(&X[q]);
        s += a.x * b.x + a.y * b.y + a.z * b.z + a.w * b.w;
    }
#pragma unroll
    for (int k = 0; k < 8; k++) {
        int q = lane + 32 * k;
        float4 a = Wh[q], b = __ldcg(&Hv[q]);
        s += a.x * b.x + a.y * b.y + a.z * b.z + a.w * b.w;
    }
    s = warp_sum(s);
    if (lane == 0) sred[group * 4 + wg] = s + bih[wg * Hdim + row] + bhh[wg * Hdim + row];
    barn(group + 1);
    if (wg == 0 && lane == 0) {
        float gi = sred[group * 4 + 0], gf = sred[group * 4 + 1];
        float gg = sred[group * 4 + 2], go = sred[group * 4 + 3];
        float cn = sigf(gf) * __ldcg(&cin[row]) + sigf(gi) * tanhf(gg);
        cout[row] = cn;
        hout[row] = sigf(go) * tanhf(cn);
    }
}

// LayerNorm over 1024 elems by one 128-thread group (named barrier barid).
__device__ void group_ln(const float* __restrict__ x, const float* __restrict__ gam,
                         const float* __restrict__ bet, const float* __restrict__ base,
                         float* __restrict__ o, volatile float* scr, int barid)
{
    int t = threadIdx.x & 127;
    int w = t >> 5, lane = t & 31;
    float xv[8]; float s = 0.f;
#pragma unroll
    for (int k = 0; k < 8; k++) { xv[k] = __ldcg(&x[t + 128 * k]); s += xv[k]; }
    s = warp_sum(s);
    if (lane == 0) scr[w] = s;
    barn(barid);
    float m = (scr[0] + scr[1] + scr[2] + scr[3]) * (1.f / Hdim);
    barn(barid);
    float q = 0.f;
#pragma unroll
    for (int k = 0; k < 8; k++) { float d = xv[k] - m; q += d * d; }
    q = warp_sum(q);
    if (lane == 0) scr[w] = q;
    barn(barid);
    float v = (scr[0] + scr[1] + scr[2] + scr[3]) * (1.f / Hdim);
    float inv = rsqrtf(v + 1e-5f);
#pragma unroll
    for (int k = 0; k < 8; k++) {
        int i = t + 128 * k;
        float r = (xv[k] - m) * inv * gam[i] + bet[i];
        if (base) r += base[i];
        o[i] = r;
    }
}

// Vocab GEMV on bf16 weights; per-row interval [v-err, v+err]; atomicMax of packed lower bound.
__device__ void phase_fc(const float* __restrict__ x, const float* __restrict__ fcb,
                         unsigned long long* swb)
{
    int wid = threadIdx.x >> 5, lane = threadIdx.x & 31;
    int gw = blockIdx.x * 32 + wid;
    const float4* X = (const float4*)x;
    float4 xc[8];
#pragma unroll
    for (int k = 0; k < 8; k++) xc[k] = __ldcg(&X[lane + ((k & 3) * 32) + ((k >> 2) ? 0 : 0)]); // placeholder, overwritten below
    // load the 32 x-values this lane needs (elements 8q..8q+7 for q = lane+32k, k<4)
#pragma unroll
    for (int k = 0; k < 4; k++) {
        int q = lane + 32 * k;
        xc[2 * k]     = __ldcg(&X[2 * q]);
        xc[2 * k + 1] = __ldcg(&X[2 * q + 1]);
    }
    unsigned long long wbest = 0ull;
    for (int r = gw; r < Vdim; r += NBLK * 32) {
        const uint4* W = (const uint4*)(g_fcw + (size_t)r * (Hdim / 2));
        float v = 0.f, a = 0.f;
#pragma unroll
        for (int k = 0; k < 4; k++) {
            int q = lane + 32 * k;
            uint4 w4 = W[q];
            float4 xA = xc[2 * k], xB = xc[2 * k + 1];
            float p0 = __uint_as_float(w4.x << 16)          * xA.x;
            float p1 = __uint_as_float(w4.x & 0xffff0000u)  * xA.y;
            float p2 = __uint_as_float(w4.y << 16)          * xA.z;
            float p3 = __uint_as_float(w4.y & 0xffff0000u)  * xA.w;
            float p4 = __uint_as_float(w4.z << 16)          * xB.x;
            float p5 = __uint_as_float(w4.z & 0xffff0000u)  * xB.y;
            float p6 = __uint_as_float(w4.w << 16)          * xB.z;
            float p7 = __uint_as_float(w4.w & 0xffff0000u)  * xB.w;
            v += p0 + p1 + p2 + p3 + p4 + p5 + p6 + p7;
            a += fabsf(p0) + fabsf(p1) + fabsf(p2) + fabsf(p3)
               + fabsf(p4) + fabsf(p5) + fabsf(p6) + fabsf(p7);
        }
        v = warp_sum(v);
        a = warp_sum(a);
        if (lane == 0) {
            v += fcb[r];
            float err = a * 0.0042f + 1e-6f;    // bf16 RN bound 2^-8 + fp32 reorder slack
            g_s.hi[r] = v + err;
            unsigned long long key = packkey(v - err, (unsigned)r);
            if (key > wbest) wbest = key;
        }
    }
    if (lane == 0) swb[wid] = wbest;
    __syncthreads();
    if (threadIdx.x == 0) {
        unsigned long long m = swb[0];
#pragma unroll
        for (int k = 1; k < 32; k++) if (swb[k] > m) m = swb[k];
        atomicMax(&g_s.lomax, m);
    }
}

// Block 0 only: exact-rescore candidates in fp32, emit token column + embed gather.
__device__ void phase_finish(const float* __restrict__ x,
                             const float* __restrict__ fcw, const float* __restrict__ fcb,
                             const float* __restrict__ embed, const float* __restrict__ tot,
                             float* __restrict__ out, int t,
                             int* s_cand, int* s_countp, float* s_red2,
                             float* s_tokp, int* s_idxp)
{
    int tid = threadIdx.x;
    int wid = tid >> 5, lane = tid & 31;
    if (tid == 0) *s_countp = 0;
    __syncthreads();
    float lo_val = key_val(g_s.lomax);
    for (int r = tid; r < Vdim; r += NTHR)
        if (__ldcg(&g_s.hi[r]) >= lo_val) {
            int p = atomicAdd(s_countp, 1);
            if (p < 256) s_cand[p] = r;
        }
    __syncthreads();
    int cnt = *s_countp; if (cnt > 256) cnt = 256;
    unsigned long long best = 0ull;           // tracked by thread 0 only
    float xv = __ldcg(&x[tid]);
    for (int ci = 0; ci < cnt; ci++) {
        int r = s_cand[ci];
        float prod = fcw[(size_t)r * Hdim + tid] * xv;
        float s = warp_sum(prod);
        if (lane == 0) s_red2[wid] = s;
        __syncthreads();
        if (tid == 0) {
            float v = 0.f;
#pragma unroll
            for (int k = 0; k < 32; k++) v += s_red2[k];
            v += fcb[r];
            unsigned long long key = packkey(v, (unsigned)r);
            if (key > best) best = key;
        }
        __syncthreads();
    }
    if (tid == 0) {
        int idx = key_idx(best);
        *s_idxp = idx;
        *s_tokp = tot[idx];
        g_s.lomax = 0ull;
    }
    __syncthreads();
    int idx = *s_idxp;
    g_s.word[tid] = embed[(size_t)idx * Hdim + tid];
    if (tid < 256) out[tid * Tlen + t] = *s_tokp;
}

__global__ void __launch_bounds__(NTHR, 1) decoder_persist(
    const float* __restrict__ features, const float* __restrict__ fc1_w, const float* __restrict__ fc1_b,
    const float* __restrict__ init_h_w, const float* __restrict__ init_h_b,
    const float* __restrict__ init_c_w, const float* __restrict__ init_c_b,
    const float* __restrict__ ln_h_g, const float* __restrict__ ln_h_b,
    const float* __restrict__ ln_c_g, const float* __restrict__ ln_c_b,
    const float* __restrict__ w_ih1, const float* __restrict__ w_hh1,
    const float* __restrict__ b_ih1, const float* __restrict__ b_hh1,
    const float* __restrict__ w_ih2, const float* __restrict__ w_hh2,
    const float* __restrict__ b_ih2, const float* __restrict__ b_hh2,
    const float* __restrict__ fc_w, const float* __restrict__ fc_b,
    const float* __restrict__ embed_w, const float* __restrict__ tot_w,
    float* __restrict__ out)
{
    __shared__ float sred[32];
    __shared__ float sln[2][8];
    __shared__ unsigned long long swb[32];
    __shared__ int s_cand[256];
    __shared__ int s_count;
    __shared__ float s_red2[32];
    __shared__ float s_tok;
    __shared__ int s_idx;

    int tid = threadIdx.x;
    int wid = tid >> 5, lane = tid & 31;
    int group = wid >> 2, wg = wid & 3;
    int row = blockIdx.x * 8 + group;

    // ---- Pro1: feat = relu(fc1_w @ features_row0 + fc1_b) ----
    if (blockIdx.x == 0 && tid == 0) g_s.lomax = 0ull;
    if (row < Hdim) {
        const float4* Wr = (const float4*)(fc1_w + (size_t)row * Edim);
        const float4* X  = (const float4*)features;
        float s = 0.f;
#pragma unroll 4
        for (int q = wg * 32 + lane; q < Edim / 4; q += 128) {
            float4 a = Wr[q], b = X[q];
            s += a.x * b.x + a.y * b.y + a.z * b.z + a.w * b.w;
        }
        s = warp_sum(s);
        if (lane == 0) sred[group * 4 + wg] = s;
        barn(group + 1);
        if (wg == 0 && lane == 0)
            g_s.feat[row] = fmaxf(sred[group*4] + sred[group*4+1] + sred[group*4+2] + sred[group*4+3]
                                  + fc1_b[row], 0.f);
    }
    grid_bar();

    // ---- Pro2: tmph/tmpc = relu(init_{h,c}_w @ feat + b) (2048 rows) ----
    for (int r = row; r < 2 * Hdim; r += NBLK * 8) {
        bool ish = r < Hdim;
        int rr = ish ? r : r - Hdim;
        const float4* Wr = (const float4*)((ish ? init_h_w : init_c_w) + (size_t)rr * Hdim);
        const float4* X  = (const float4*)g_s.feat;
        int q = wg * 32 + lane;
        float4 a0 = Wr[q],       b0 = __ldcg(&X[q]);
        float4 a1 = Wr[q + 128], b1 = __ldcg(&X[q + 128]);
        float s = a0.x*b0.x + a0.y*b0.y + a0.z*b0.z + a0.w*b0.w
                + a1.x*b1.x + a1.y*b1.y + a1.z*b1.z + a1.w*b1.w;
        s = warp_sum(s);
        if (lane == 0) sred[group * 4 + wg] = s;
        barn(group + 1);
        if (wg == 0 && lane == 0) {
            float val = fmaxf(sred[group*4] + sred[group*4+1] + sred[group*4+2] + sred[group*4+3]
                              + (ish ? init_h_b[rr] : init_c_b[rr]), 0.f);
            if (ish) g_s.tmph[rr] = val; else g_s.tmpc[rr] = val;
        }
        barn(group + 1);   // protect sred before next loop iteration
    }
    grid_bar();

    // ---- Pro3: h/c = LN(tmph/tmpc) (block NBLK-1) ; bf16-convert fc_w (other blocks) ----
    if (blockIdx.x == NBLK - 1) {
        if (group == 0)      group_ln(g_s.tmph, ln_h_g, ln_h_b, nullptr, g_s.h, sln[0], 1);
        else if (group == 1) group_ln(g_s.tmpc, ln_c_g, ln_c_b, nullptr, g_s.c, sln[1], 2);
    } else {
        int lt = blockIdx.x * NTHR + tid;
        const float4* src = (const float4*)fc_w;
        uint2* dst = (uint2*)g_fcw;
        const int total = Vdim * (Hdim / 4);
        for (int i = lt; i < total; i += (NBLK - 1) * NTHR) {
            float4 f = src[i];
            unsigned u0 = (unsigned)__bfloat16_as_ushort(__float2bfloat16(f.x))
                        | ((unsigned)__bfloat16_as_ushort(__float2bfloat16(f.y)) << 16);
            unsigned u1 = (unsigned)__bfloat16_as_ushort(__float2bfloat16(f.z))
                        | ((unsigned)__bfloat16_as_ushort(__float2bfloat16(f.w)) << 16);
            dst[i] = make_uint2(u0, u1);
        }
    }
    grid_bar();

    // ---- decode steps ----
    for (int t = 0; t < Tlen; t++) {
        int p = t & 1;
        int pp = (t - 1) & 1;

        // P1: cell1
        if (t == 0)
            phase_cell(g_s.feat, g_s.h, g_s.c, w_ih1, w_hh1, b_ih1, b_hh1,
                       g_s.h1, g_s.c1, sred, row, group, wg, lane);
        else
            phase_cell(g_s.word, g_s.tmph, g_s.tmpc, w_ih1, w_hh1, b_ih1, b_hh1,
                       g_s.h1, g_s.c1, sred, row, group, wg, lane);
        grid_bar();

        // P2: cell2 ; block NBLK-1 groups 0/1 compute next step's LN(h1)+h / LN(c1)+c
        if (blockIdx.x == NBLK - 1) {
            if (group == 0)      group_ln(g_s.h1, ln_h_g, ln_h_b, g_s.h, g_s.tmph, sln[0], 1);
            else if (group == 1) group_ln(g_s.c1, ln_c_g, ln_c_b, g_s.c, g_s.tmpc, sln[1], 2);
        }
        phase_cell(g_s.h1,
                   (t == 0) ? g_s.h : g_s.h2[pp],
                   (t == 0) ? g_s.c : g_s.c2[pp],
                   w_ih2, w_hh2, b_ih2, b_hh2,
                   g_s.h2[p], g_s.c2[p], sred, row, group, wg, lane);
        grid_bar();

        // P3: cell3
        phase_cell(g_s.h2[p],
                   (t == 0) ? g_s.h : g_s.h3[pp],
                   (t == 0) ? g_s.c : g_s.c3[pp],
                   w_ih2, w_hh2, b_ih2, b_hh2,
                   g_s.h3[p], g_s.c3[p], sred, row, group, wg, lane);
        grid_bar();

        // P4: vocab GEMV (bf16) + interval argmax bound
        phase_fc(g_s.h3[p], fc_b, swb);
        grid_bar();

        // P5: exact refine + token/word emit (block 0)
        if (blockIdx.x == 0)
            phase_finish(g_s.h3[p], fc_w, fc_b, embed_w, tot_w, out, t,
                         s_cand, &s_count, s_red2, &s_tok, &s_idx);
        grid_bar();
    }
}

extern "C" void kernel_launch(void* const* d_in, const int* in_sizes, int n_in,
                              void* d_out, int out_size) {
    const float* features  = (const float*)d_in[0];
    const float* fc1_w     = (const float*)d_in[1];
    const float* fc1_b     = (const float*)d_in[2];
    const float* init_h_w  = (const float*)d_in[3];
    const float* init_h_b  = (const float*)d_in[4];
    const float* init_c_w  = (const float*)d_in[5];
    const float* init_c_b  = (const float*)d_in[6];
    const float* ln_h_g    = (const float*)d_in[7];
    const float* ln_h_b    = (const float*)d_in[8];
    const float* ln_c_g    = (const float*)d_in[9];
    const float* ln_c_b    = (const float*)d_in[10];
    const float* w_ih1     = (const float*)d_in[11];
    const float* w_hh1     = (const float*)d_in[12];
    const float* b_ih1     = (const float*)d_in[13];
    const float* b_hh1     = (const float*)d_in[14];
    const float* w_ih2     = (const float*)d_in[15];
    const float* w_hh2     = (const float*)d_in[16];
    const float* b_ih2     = (const float*)d_in[17];
    const float* b_hh2     = (const float*)d_in[18];
    const float* fc_w      = (const float*)d_in[19];
    const float* fc_b      = (const float*)d_in[20];
    const float* embed_w   = (const float*)d_in[21];
    const float* totoken_w = (const float*)d_in[22];
    float* out = (float*)d_out;

    decoder_persist<<<NBLK, NTHR>>>(
        features, fc1_w, fc1_b, init_h_w, init_h_b, init_c_w, init_c_b,
        ln_h_g, ln_h_b, ln_c_g, ln_c_b,
        w_ih1, w_hh1, b_ih1, b_hh1, w_ih2, w_hh2, b_ih2, b_hh2,
        fc_w, fc_b, embed_w, totoken_w, out);
}

// round 4
// speedup vs baseline: 1.2288x; 1.2288x over previous
#include <cuda_runtime.h>
#include <cuda_bf16.h>
#include <cstdint>
#include <cstddef>

#define Hdim 1024
#define Edim 18432
#define Vdim 32000
#define Tlen 15

struct State {
    float feat[Hdim];
    float h[Hdim], c[Hdim];
    float tmph[Hdim], tmpc[Hdim];
    float h1[Hdim], c1[Hdim];
    float h2[2][Hdim], c2[2][Hdim];
    float h3[2][Hdim], c3[2][Hdim];
    float word[Hdim];
    float hi[Vdim];
    unsigned long long lomax;
    unsigned ticket1, ticket2;
};
__device__ State g_s;
__device__ unsigned g_fcw[(size_t)Vdim * (Hdim / 2)];   // bf16x2-packed fc_w (65.5 MB)

// ---------- helpers ----------
__device__ __forceinline__ float sigf(float x) { return 1.0f / (1.0f + expf(-x)); }

__device__ __forceinline__ float warp_sum(float s) {
#pragma unroll
    for (int o = 16; o; o >>= 1) s += __shfl_xor_sync(0xffffffffu, s, o);
    return s;
}

// block reduce across 256 threads (8 warps)
__device__ __forceinline__ float block_sum(float s) {
    __shared__ float sm[8];
    __shared__ float outv;
    int w = threadIdx.x >> 5, lane = threadIdx.x & 31;
    s = warp_sum(s);
    if (lane == 0) sm[w] = s;
    __syncthreads();
    if (w == 0) {
        float r = (lane < 8) ? sm[lane] : 0.0f;
        r = warp_sum(r);
        if (lane == 0) outv = r;
    }
    __syncthreads();
    float res = outv;
    __syncthreads();
    return res;
}

__device__ __forceinline__ unsigned long long packkey(float v, unsigned idx) {
    unsigned u = __float_as_uint(v);
    u = (u & 0x80000000u) ? ~u : (u | 0x80000000u);
    return ((unsigned long long)u << 32) | (unsigned long long)(0xFFFFFFFFu - idx);
}
__device__ __forceinline__ float key_val(unsigned long long k) {
    unsigned u = (unsigned)(k >> 32);
    u = (u & 0x80000000u) ? (u ^ 0x80000000u) : ~u;
    return __uint_as_float(u);
}
__device__ __forceinline__ int key_idx(unsigned long long k) {
    return (int)(0xFFFFFFFFu - (unsigned)(k & 0xFFFFFFFFull));
}

// ---------- L2 eviction policies via createpolicy + cache_hint ----------
__device__ __forceinline__ unsigned long long pol_first() {
    unsigned long long p;
    asm("createpolicy.fractional.L2::evict_first.b64 %0, 1.0;" : "=l"(p));
    return p;
}
__device__ __forceinline__ unsigned long long pol_last() {
    unsigned long long p;
    asm("createpolicy.fractional.L2::evict_last.b64 %0, 1.0;" : "=l"(p));
    return p;
}
__device__ __forceinline__ float4 ld_f4_hint(const float4* p, unsigned long long pol) {
    float4 v;
    asm("ld.global.L2::cache_hint.v4.f32 {%0,%1,%2,%3}, [%4], %5;"
        : "=f"(v.x), "=f"(v.y), "=f"(v.z), "=f"(v.w) : "l"(p), "l"(pol));
    return v;
}
__device__ __forceinline__ uint4 ld_u4_hint(const uint4* p, unsigned long long pol) {
    uint4 v;
    asm("ld.global.L2::cache_hint.v4.u32 {%0,%1,%2,%3}, [%4], %5;"
        : "=r"(v.x), "=r"(v.y), "=r"(v.z), "=r"(v.w) : "l"(p), "l"(pol));
    return v;
}
__device__ __forceinline__ void st_u2_hint(uint2* p, uint2 v, unsigned long long pol) {
    asm volatile("st.global.L2::cache_hint.v2.u32 [%0], {%1,%2}, %3;"
                 :: "l"(p), "r"(v.x), "r"(v.y), "l"(pol) : "memory");
}

// ---------- LayerNorm by one 256-thread block ----------
__device__ void ln256(const float* __restrict__ x, const float* __restrict__ g,
                      const float* __restrict__ b, const float* __restrict__ base,
                      float* __restrict__ o) {
    float xv[4];
    float s = 0.f;
#pragma unroll
    for (int k = 0; k < 4; k++) { xv[k] = x[threadIdx.x + 256 * k]; s += xv[k]; }
    float m = block_sum(s) * (1.f / Hdim);
    float q = 0.f;
#pragma unroll
    for (int k = 0; k < 4; k++) { float d = xv[k] - m; q += d * d; }
    float v = block_sum(q) * (1.f / Hdim);
    float inv = rsqrtf(v + 1e-5f);
#pragma unroll
    for (int k = 0; k < 4; k++) {
        int i = threadIdx.x + 256 * k;
        float r = (xv[k] - m) * inv * g[i] + b[i];
        if (base) r += base[i];
        o[i] = r;
    }
}

// ---------- prologue: fc1 rows (blocks < Hdim) + bf16 convert (rest) ----------
__global__ void __launch_bounds__(256) k_pro1(
    const float* __restrict__ feats, const float* __restrict__ w,
    const float* __restrict__ bias, const float* __restrict__ fcw32) {
    unsigned long long pf = pol_first();
    if (blockIdx.x < Hdim) {
        int j = blockIdx.x;
        const float4* Wr = (const float4*)(w + (size_t)j * Edim);
        const float4* X  = (const float4*)feats;
        float s = 0.f;
        for (int i = threadIdx.x; i < Edim / 4; i += 256) {
            float4 a = ld_f4_hint(&Wr[i], pf), v = X[i];
            s += a.x * v.x + a.y * v.y + a.z * v.z + a.w * v.w;
        }
        s = block_sum(s);
        if (threadIdx.x == 0) g_s.feat[j] = fmaxf(s + bias[j], 0.f);
    } else {
        unsigned long long pl = pol_last();
        const float4* src = (const float4*)fcw32;
        uint2* dst = (uint2*)g_fcw;
        const int total = Vdim * (Hdim / 4);
        int start  = (blockIdx.x - Hdim) * 256 + threadIdx.x;
        int stride = (gridDim.x - Hdim) * 256;
        for (int i = start; i < total; i += stride) {
            float4 f = ld_f4_hint(&src[i], pf);
            uint2 u;
            u.x = (unsigned)__bfloat16_as_ushort(__float2bfloat16(f.x))
                | ((unsigned)__bfloat16_as_ushort(__float2bfloat16(f.y)) << 16);
            u.y = (unsigned)__bfloat16_as_ushort(__float2bfloat16(f.z))
                | ((unsigned)__bfloat16_as_ushort(__float2bfloat16(f.w)) << 16);
            st_u2_hint(&dst[i], u, pl);
        }
    }
}

// ---------- init h/c GEMVs + (last block) prologue LayerNorms ----------
__global__ void __launch_bounds__(256) k_init2(
    const float* __restrict__ wh, const float* __restrict__ bh,
    const float* __restrict__ wc, const float* __restrict__ bc,
    const float* __restrict__ lnhg, const float* __restrict__ lnhb,
    const float* __restrict__ lncg, const float* __restrict__ lncb) {
    unsigned long long pf = pol_first();
    int j = blockIdx.x;
    bool ish = j < Hdim;
    int r = ish ? j : j - Hdim;
    const float4* Wr = (const float4*)((ish ? wh : wc) + (size_t)r * Hdim);
    const float4* X  = (const float4*)g_s.feat;
    float4 a = ld_f4_hint(&Wr[threadIdx.x], pf), v = X[threadIdx.x];
    float s = a.x * v.x + a.y * v.y + a.z * v.z + a.w * v.w;
    s = block_sum(s);
    __shared__ bool lastb;
    if (threadIdx.x == 0) {
        float val = fmaxf(s + (ish ? bh[r] : bc[r]), 0.f);
        if (ish) g_s.tmph[r] = val; else g_s.tmpc[r] = val;
        __threadfence();
        lastb = (atomicAdd(&g_s.ticket1, 1u) == 2u * Hdim - 1u);
    }
    __syncthreads();
    if (!lastb) return;
    ln256(g_s.tmph, lnhg, lnhb, nullptr, g_s.h);
    ln256(g_s.tmpc, lncg, lncb, nullptr, g_s.c);
    if (threadIdx.x == 0) g_s.ticket1 = 0;
}

// ---------- LSTM cell (block j = hidden row j; warps 0-3: W_ih gates, 4-7: W_hh) ----------
// EVL: evict_last on weights (w2, reused). FUSELN: blocks Hdim/Hdim+1 do LN for next step.
template <bool EVL, bool FUSELN>
__global__ void __launch_bounds__(256) k_cell(
    const float* __restrict__ x, const float* __restrict__ hin, const float* __restrict__ cin,
    const float* __restrict__ wih, const float* __restrict__ whh,
    const float* __restrict__ bih, const float* __restrict__ bhh,
    float* __restrict__ hout, float* __restrict__ cout,
    const float* __restrict__ lnhg, const float* __restrict__ lnhb,
    const float* __restrict__ lncg, const float* __restrict__ lncb) {
    if (FUSELN && blockIdx.x >= Hdim) {
        bool ish = (blockIdx.x == Hdim);
        ln256(ish ? g_s.h1 : g_s.c1,
              ish ? lnhg : lncg, ish ? lnhb : lncb,
              ish ? g_s.h : g_s.c,
              ish ? g_s.tmph : g_s.tmpc);
        return;
    }
    unsigned long long pol = EVL ? pol_last() : pol_first();
    int j = blockIdx.x;
    int w = threadIdx.x >> 5, lane = threadIdx.x & 31;
    const float* Wm  = (w < 4) ? wih : whh;
    const float* vec = (w < 4) ? x : hin;
    int row = j + (w & 3) * Hdim;
    const float4* Wr = (const float4*)(Wm + (size_t)row * Hdim);
    const float4* v4 = (const float4*)vec;
    float s = 0.f;
#pragma unroll
    for (int i = 0; i < 8; i++) {
        float4 a = ld_f4_hint(&Wr[lane + 32 * i], pol);
        float4 b = v4[lane + 32 * i];
        s += a.x * b.x + a.y * b.y + a.z * b.z + a.w * b.w;
    }
    s = warp_sum(s);
    __shared__ float red[8];
    if (lane == 0) red[w] = s;
    __syncthreads();
    if (threadIdx.x == 0) {
        float gi = red[0] + red[4] + bih[j]            + bhh[j];
        float gf = red[1] + red[5] + bih[j + Hdim]     + bhh[j + Hdim];
        float gg = red[2] + red[6] + bih[j + 2 * Hdim] + bhh[j + 2 * Hdim];
        float go = red[3] + red[7] + bih[j + 3 * Hdim] + bhh[j + 3 * Hdim];
        float cn = sigf(gf) * cin[j] + sigf(gi) * tanhf(gg);
        cout[j] = cn;
        hout[j] = sigf(go) * tanhf(cn);
    }
}

// ---------- vocab GEMV (bf16) + interval bound + (last block) exact refine & emit ----------
__global__ void __launch_bounds__(256) k_fcb(
    const float* __restrict__ x, const float* __restrict__ fcb,
    const float* __restrict__ fcw32, const float* __restrict__ embed,
    const float* __restrict__ tot, float* __restrict__ out, int t) {
    unsigned long long pl = pol_last();
    int tid = threadIdx.x, wid = tid >> 5, lane = tid & 31;
    const float4* X = (const float4*)x;
    float4 xc[8];
#pragma unroll
    for (int k = 0; k < 4; k++) {
        int q = lane + 32 * k;
        xc[2 * k]     = X[2 * q];
        xc[2 * k + 1] = X[2 * q + 1];
    }
    unsigned long long wbest = 0ull;
    int r0 = (blockIdx.x * 8 + wid) * 4;
#pragma unroll
    for (int rr = 0; rr < 4; rr++) {
        int r = r0 + rr;
        const uint4* W = (const uint4*)(g_fcw + (size_t)r * (Hdim / 2));
        float v = 0.f, a = 0.f;
#pragma unroll
        for (int k = 0; k < 4; k++) {
            uint4 w4 = ld_u4_hint(&W[lane + 32 * k], pl);
            float4 xA = xc[2 * k], xB = xc[2 * k + 1];
            float p0 = __uint_as_float(w4.x << 16)         * xA.x;
            float p1 = __uint_as_float(w4.x & 0xffff0000u) * xA.y;
            float p2 = __uint_as_float(w4.y << 16)         * xA.z;
            float p3 = __uint_as_float(w4.y & 0xffff0000u) * xA.w;
            float p4 = __uint_as_float(w4.z << 16)         * xB.x;
            float p5 = __uint_as_float(w4.z & 0xffff0000u) * xB.y;
            float p6 = __uint_as_float(w4.w << 16)         * xB.z;
            float p7 = __uint_as_float(w4.w & 0xffff0000u) * xB.w;
            v += p0 + p1 + p2 + p3 + p4 + p5 + p6 + p7;
            a += fabsf(p0) + fabsf(p1) + fabsf(p2) + fabsf(p3)
               + fabsf(p4) + fabsf(p5) + fabsf(p6) + fabsf(p7);
        }
        v = warp_sum(v);
        a = warp_sum(a);
        if (lane == 0) {
            v += fcb[r];
            float err = a * 0.0042f + 1e-6f;
            g_s.hi[r] = v + err;
            unsigned long long key = packkey(v - err, (unsigned)r);
            if (key > wbest) wbest = key;
        }
    }
    __shared__ unsigned long long sb[8];
    __shared__ bool lastb;
    if (lane == 0) sb[wid] = wbest;
    __syncthreads();
    if (tid == 0) {
        unsigned long long m = sb[0];
#pragma unroll
        for (int k = 1; k < 8; k++) if (sb[k] > m) m = sb[k];
        atomicMax(&g_s.lomax, m);
        __threadfence();
        lastb = (atomicAdd(&g_s.ticket2, 1u) == gridDim.x - 1u);
    }
    __syncthreads();
    if (!lastb) return;

    // ------- finish (sole surviving block; all hi/lomax writes fenced-visible) -------
    __shared__ int cand[64];
    __shared__ int cnt;
    __shared__ unsigned long long s_lom;
    __shared__ float red2[8];
    __shared__ int s_idx;
    __shared__ float s_tok;
    if (tid == 0) { cnt = 0; s_lom = atomicAdd(&g_s.lomax, 0ull); }
    __syncthreads();
    float lo = key_val(s_lom);
    for (int r = tid; r < Vdim; r += 256)
        if (g_s.hi[r] >= lo) {
            int p = atomicAdd(&cnt, 1);
            if (p < 64) cand[p] = r;
        }
    __syncthreads();
    int n = cnt < 64 ? cnt : 64;
    unsigned long long best = 0ull;   // tracked by thread 0
    float4 x4 = X[tid];
    for (int ci = 0; ci < n; ci++) {
        int r = cand[ci];
        const float4* Wr = (const float4*)(fcw32 + (size_t)r * Hdim);
        float4 a = Wr[tid];
        float prod = a.x * x4.x + a.y * x4.y + a.z * x4.z + a.w * x4.w;
        prod = warp_sum(prod);
        if (lane == 0) red2[wid] = prod;
        __syncthreads();
        if (tid == 0) {
            float v = red2[0] + red2[1] + red2[2] + red2[3]
                    + red2[4] + red2[5] + red2[6] + red2[7];
            v += fcb[r];
            unsigned long long key = packkey(v, (unsigned)r);
            if (key > best) best = key;
        }
        __syncthreads();
    }
    if (tid == 0) {
        s_idx = key_idx(best);
        s_tok = tot[s_idx];
        g_s.lomax = 0ull;
        g_s.ticket2 = 0u;
    }
    __syncthreads();
    int idx = s_idx;
    ((float4*)g_s.word)[tid] = ((const float4*)(embed + (size_t)idx * Hdim))[tid];
    out[tid * Tlen + t] = s_tok;   // batch == 256 == blockDim
}

extern "C" void kernel_launch(void* const* d_in, const int* in_sizes, int n_in,
                              void* d_out, int out_size) {
    const float* features  = (const float*)d_in[0];
    const float* fc1_w     = (const float*)d_in[1];
    const float* fc1_b     = (const float*)d_in[2];
    const float* init_h_w  = (const float*)d_in[3];
    const float* init_h_b  = (const float*)d_in[4];
    const float* init_c_w  = (const float*)d_in[5];
    const float* init_c_b  = (const float*)d_in[6];
    const float* ln_h_g    = (const float*)d_in[7];
    const float* ln_h_b    = (const float*)d_in[8];
    const float* ln_c_g    = (const float*)d_in[9];
    const float* ln_c_b    = (const float*)d_in[10];
    const float* w_ih1     = (const float*)d_in[11];
    const float* w_hh1     = (const float*)d_in[12];
    const float* b_ih1     = (const float*)d_in[13];
    const float* b_hh1     = (const float*)d_in[14];
    const float* w_ih2     = (const float*)d_in[15];
    const float* w_hh2     = (const float*)d_in[16];
    const float* b_ih2     = (const float*)d_in[17];
    const float* b_hh2     = (const float*)d_in[18];
    const float* fc_w      = (const float*)d_in[19];
    const float* fc_b      = (const float*)d_in[20];
    const float* embed_w   = (const float*)d_in[21];
    const float* totoken_w = (const float*)d_in[22];
    float* out = (float*)d_out;

    State* S = nullptr;
    cudaGetSymbolAddress((void**)&S, g_s);

    // prologue: feat GEMV + bf16 convert (one kernel), then init GEMVs + LN (one kernel)
    k_pro1<<<Hdim + 1480, 256>>>(features, fc1_w, fc1_b, fc_w);
    k_init2<<<2 * Hdim, 256>>>(init_h_w, init_h_b, init_c_w, init_c_b,
                               ln_h_g, ln_h_b, ln_c_g, ln_c_b);

    // ---- step 0 ----
    k_cell<false, false><<<Hdim, 256>>>(S->feat, S->h, S->c,
        w_ih1, w_hh1, b_ih1, b_hh1, S->h1, S->c1,
        nullptr, nullptr, nullptr, nullptr);
    k_cell<true, true><<<Hdim + 2, 256>>>(S->h1, S->h, S->c,
        w_ih2, w_hh2, b_ih2, b_hh2, S->h2[0], S->c2[0],
        ln_h_g, ln_h_b, ln_c_g, ln_c_b);
    k_cell<true, false><<<Hdim, 256>>>(S->h2[0], S->h, S->c,
        w_ih2, w_hh2, b_ih2, b_hh2, S->h3[0], S->c3[0],
        nullptr, nullptr, nullptr, nullptr);
    k_fcb<<<Vdim / 32, 256>>>(S->h3[0], fc_b, fc_w, embed_w, totoken_w, out, 0);

    // ---- steps 1..14 ----
    int p = 0;
    for (int t = 1; t < Tlen; t++) {
        int q = 1 - p;
        k_cell<false, false><<<Hdim, 256>>>(S->word, S->tmph, S->tmpc,
            w_ih1, w_hh1, b_ih1, b_hh1, S->h1, S->c1,
            nullptr, nullptr, nullptr, nullptr);
        k_cell<true, true><<<Hdim + 2, 256>>>(S->h1, S->h2[p], S->c2[p],
            w_ih2, w_hh2, b_ih2, b_hh2, S->h2[q], S->c2[q],
            ln_h_g, ln_h_b, ln_c_g, ln_c_b);
        k_cell<true, false><<<Hdim, 256>>>(S->h2[q], S->h3[p], S->c3[p],
            w_ih2, w_hh2, b_ih2, b_hh2, S->h3[q], S->c3[q],
            nullptr, nullptr, nullptr, nullptr);
        k_fcb<<<Vdim / 32, 256>>>(S->h3[q], fc_b, fc_w, embed_w, totoken_w, out, t);
        p = q;
    }
}